// round 12
// baseline (speedup 1.0000x reference)
#include <cuda_runtime.h>
#include <cuda_bf16.h>

#define B_SZ    8
#define T_SZ    2048
#define VOCAB   8192
#define NT      1024
#define SPLIT   8                    // CTAs per batch row
#define SLICE   (VOCAB / SPLIT)      // 1024 vocab entries per CTA

__global__ __launch_bounds__(NT)
void constrained_attn_kernel(const int* __restrict__ x,
                             const float* __restrict__ params,
                             float* __restrict__ out)
{
    __shared__ float zcorr;            // sparse softmax-Z correction

    const int b     = blockIdx.x >> 3;      // batch row
    const int slice = blockIdx.x & 7;       // vocab slice id
    const int tid   = threadIdx.x;

    const int* xb = x + b * T_SZ;
    float* oslice = out + b * VOCAB + slice * SLICE;   // this CTA's 4 KB of out

    if (tid == 0) zcorr = 0.0f;

    // ---- zero this CTA's output slice directly (256 × STG.128) ----
    if (tid < SLICE / 4)
        reinterpret_cast<float4*>(oslice)[tid] = make_float4(0.f, 0.f, 0.f, 0.f);

    // ---- direct gmem token reads: thread owns t0 = 2*tid, t1 = 2*tid+1 ----
    const int2 cur  = reinterpret_cast<const int2*>(xb)[tid];
    const int2 prev = (tid > 0) ? reinterpret_cast<const int2*>(xb)[tid - 1]
                                : make_int2(-1, -1);               // sentinels
    const int a0 = prev.x;   // toks[t0-2]
    const int a1 = prev.y;   // toks[t0-1]
    const int b0 = cur.x;    // toks[t0]
    const int b1 = cur.y;    // toks[t1]

    // query tokens (uniform-address LDG -> broadcast)
    const int q0 = xb[T_SZ - 1];
    const int q1 = xb[T_SZ - 2];
    const int q2 = xb[T_SZ - 3];

    const float p00 = params[0], p01 = params[1], p02 = params[2];
    const float p10 = params[3], p11 = params[4], p12 = params[5];
    const float p20 = params[6], p21 = params[7], p22 = params[8];

    // score(t) = sum_{i,j} p[i][j] * [q_i == toks[t-j]]
    float s0, s1;
    s0  = (q0 == b0) ? p00 : 0.0f;        // t0 keys: (b0, a1, a0)
    s0 += (q0 == a1) ? p01 : 0.0f;
    s0 += (q0 == a0) ? p02 : 0.0f;
    s0 += (q1 == b0) ? p10 : 0.0f;
    s0 += (q1 == a1) ? p11 : 0.0f;
    s0 += (q1 == a0) ? p12 : 0.0f;
    s0 += (q2 == b0) ? p20 : 0.0f;
    s0 += (q2 == a1) ? p21 : 0.0f;
    s0 += (q2 == a0) ? p22 : 0.0f;

    s1  = (q0 == b1) ? p00 : 0.0f;        // t1 keys: (b1, b0, a1)
    s1 += (q0 == b0) ? p01 : 0.0f;
    s1 += (q0 == a1) ? p02 : 0.0f;
    s1 += (q1 == b1) ? p10 : 0.0f;
    s1 += (q1 == b0) ? p11 : 0.0f;
    s1 += (q1 == a1) ? p12 : 0.0f;
    s1 += (q2 == b1) ? p20 : 0.0f;
    s1 += (q2 == b0) ? p21 : 0.0f;
    s1 += (q2 == a1) ? p22 : 0.0f;

    const bool masked1 = (tid == NT - 1);   // t1 == T-1 is masked out

    // Z = 2047 + sum over matched tokens of (exp(s)-1); matches are rare (~8/row).
    const float e0 = __expf(s0);
    const float e1 = masked1 ? 0.0f : __expf(s1);
    float corr = 0.0f;
    if (s0 != 0.0f)             corr += e0 - 1.0f;
    if (s1 != 0.0f && !masked1) corr += e1 - 1.0f;
    if (corr != 0.0f) atomicAdd(&zcorr, corr);

    __syncthreads();   // orders: zero-STGs + zcorr before the scatter atomics

    const float inv = __fdividef(1.0f, 2047.0f + zcorr);

    // ---- scatter straight into out (global no-return atomics, ~256/CTA) ----
    if ((b0 >> 10) == slice)             atomicAdd(&oslice[b0 & (SLICE - 1)], e0 * inv);
    if ((b1 >> 10) == slice && !masked1) atomicAdd(&oslice[b1 & (SLICE - 1)], e1 * inv);
}

extern "C" void kernel_launch(void* const* d_in, const int* in_sizes, int n_in,
                              void* d_out, int out_size)
{
    const int*   x      = (const int*)d_in[0];     // (8, 2048) int32
    const float* params = (const float*)d_in[1];   // (3, 3) float32
    float*       out    = (float*)d_out;           // (8, 8192) float32

    (void)in_sizes; (void)n_in; (void)out_size;
    constrained_attn_kernel<<<B_SZ * SPLIT, NT>>>(x, params, out);
}

// round 15
// speedup vs baseline: 1.0386x; 1.0386x over previous
#include <cuda_runtime.h>
#include <cuda_bf16.h>

#define B_SZ    8
#define T_SZ    2048
#define VOCAB   8192
#define NT      512                  // 16 warps per CTA
#define SPLIT   16                   // CTAs (vocab slices) per batch row
#define SLICE   (VOCAB / SPLIT)      // 512 vocab entries per CTA
#define TPT     4                    // tokens per thread

__global__ __launch_bounds__(NT)
void constrained_attn_kernel(const int* __restrict__ x,
                             const float* __restrict__ params,
                             float* __restrict__ out)
{
    __shared__ float vslice[SLICE];    // 2 KB — this CTA's vocab slice
    __shared__ float zcorr;            // sparse softmax-Z correction

    const int b     = blockIdx.x >> 4;      // batch row
    const int slice = blockIdx.x & 15;      // vocab slice id
    const int tid   = threadIdx.x;

    const int* xb = x + b * T_SZ;

    // init smem (covered by BAR 1): one float per thread
    vslice[tid] = 0.0f;
    if (tid == 0) zcorr = 0.0f;

    // ---- tokens: thread owns t0 = 4*tid .. 4*tid+3 ----
    const int4 cur = reinterpret_cast<const int4*>(xb)[tid];     // toks[t0..t0+3]
    // neighbors toks[t0-2], toks[t0-1]: int2 at element offset 4*tid-2 (8B aligned)
    const int2 prev = (tid > 0)
        ? *reinterpret_cast<const int2*>(xb + 4 * tid - 2)
        : make_int2(-1, -1);                                     // sentinels
    const int c0 = cur.x, c1 = cur.y, c2 = cur.z, c3 = cur.w;
    const int pm2 = prev.x;   // toks[t0-2]
    const int pm1 = prev.y;   // toks[t0-1]

    // query tokens (uniform-address LDG -> broadcast)
    const int q0 = xb[T_SZ - 1];
    const int q1 = xb[T_SZ - 2];
    const int q2 = xb[T_SZ - 3];

    const float p00 = params[0], p01 = params[1], p02 = params[2];
    const float p10 = params[3], p11 = params[4], p12 = params[5];
    const float p20 = params[6], p21 = params[7], p22 = params[8];

    // score(t) = sum_{i,j} p[i][j] * [q_i == toks[t-j]]
    auto score = [&](int k0, int k1, int k2) -> float {
        float s;
        s  = (q0 == k0) ? p00 : 0.0f;
        s += (q0 == k1) ? p01 : 0.0f;
        s += (q0 == k2) ? p02 : 0.0f;
        s += (q1 == k0) ? p10 : 0.0f;
        s += (q1 == k1) ? p11 : 0.0f;
        s += (q1 == k2) ? p12 : 0.0f;
        s += (q2 == k0) ? p20 : 0.0f;
        s += (q2 == k1) ? p21 : 0.0f;
        s += (q2 == k2) ? p22 : 0.0f;
        return s;
    };

    const float s0 = score(c0, pm1, pm2);
    const float s1 = score(c1, c0,  pm1);
    const float s2 = score(c2, c1,  c0);
    const float s3 = score(c3, c2,  c1);

    const bool masked3 = (tid == NT - 1);   // token 4*tid+3 == T-1 is masked

    // Z = 2047 + sum over matched tokens of (exp(s)-1); matches are rare (~8/row).
    const float e0 = __expf(s0);
    const float e1 = __expf(s1);
    const float e2 = __expf(s2);
    const float e3 = masked3 ? 0.0f : __expf(s3);

    float corr = 0.0f;
    if (s0 != 0.0f)             corr += e0 - 1.0f;
    if (s1 != 0.0f)             corr += e1 - 1.0f;
    if (s2 != 0.0f)             corr += e2 - 1.0f;
    if (s3 != 0.0f && !masked3) corr += e3 - 1.0f;
    if (corr != 0.0f) atomicAdd(&zcorr, corr);

    __syncthreads();   // BAR 1: zcorr + vslice zero visible

    const float inv = __fdividef(1.0f, 2047.0f + zcorr);

    // ---- scatter: only tokens in this CTA's 512-entry slice (~128/CTA) ----
    if ((c0 >> 9) == slice)             atomicAdd(&vslice[c0 & (SLICE - 1)], e0 * inv);
    if ((c1 >> 9) == slice)             atomicAdd(&vslice[c1 & (SLICE - 1)], e1 * inv);
    if ((c2 >> 9) == slice)             atomicAdd(&vslice[c2 & (SLICE - 1)], e2 * inv);
    if ((c3 >> 9) == slice && !masked3) atomicAdd(&vslice[c3 & (SLICE - 1)], e3 * inv);

    __syncthreads();   // BAR 2

    // ---- store this CTA's 2 KB slice (coalesced, 1 float per thread) ----
    out[b * VOCAB + slice * SLICE + tid] = vslice[tid];
}

extern "C" void kernel_launch(void* const* d_in, const int* in_sizes, int n_in,
                              void* d_out, int out_size)
{
    const int*   x      = (const int*)d_in[0];     // (8, 2048) int32
    const float* params = (const float*)d_in[1];   // (3, 3) float32
    float*       out    = (float*)d_out;           // (8, 8192) float32

    (void)in_sizes; (void)n_in; (void)out_size;
    constrained_attn_kernel<<<B_SZ * SPLIT, NT>>>(x, params, out);
}